// round 17
// baseline (speedup 1.0000x reference)
#include <cuda_runtime.h>
#include <math.h>

#define NN 1024
#define HEADS 8
#define EDIM 16
#define TN 32          // n-tile per block (fused)
#define TM 32          // m chunk staged per iteration
#define MSPLIT 8       // m-range split across blocks
#define CHUNKS 4       // chunks per block: TM*CHUNKS = 128 m

typedef unsigned long long ull;

// -------- device scratch (allocation-free) --------
__device__ float g_q[NN*128];
__device__ float g_k[NN*128];
__device__ float g_v[NN*128];
__device__ float g_Sp [MSPLIT*(size_t)NN*128];   // partial S  per m-split
__device__ float g_avp[MSPLIT*(size_t)NN*128];   // partial av per m-split
__device__ float g_dnp[MSPLIT*NN*HEADS];         // partial den

// ---- packed f32x2 helpers (sm_103a) ----
__device__ __forceinline__ ull pk2(float lo, float hi) {
    ull r; asm("mov.b64 %0, {%1,%2};" : "=l"(r) : "f"(lo), "f"(hi)); return r;
}
__device__ __forceinline__ void upk2(float& lo, float& hi, ull v) {
    asm("mov.b64 {%0,%1}, %2;" : "=f"(lo), "=f"(hi) : "l"(v));
}
__device__ __forceinline__ ull fma2(ull a, ull b, ull c) {
    ull d; asm("fma.rn.f32x2 %0, %1, %2, %3;" : "=l"(d) : "l"(a), "l"(b), "l"(c)); return d;
}
__device__ __forceinline__ ull add2(ull a, ull b) {
    ull d; asm("add.rn.f32x2 %0, %1, %2;" : "=l"(d) : "l"(a), "l"(b)); return d;
}

// smem layout for k_fused (float offsets): ks[32][164], vs[32][164], ms[32][33]
#define K_OFF 0
#define V_OFF 5248
#define M_OFF 10496
#define SM_FLOATS (10496 + 1056)     // 11552 floats = 46.2 KB -> 2 blocks/SM

// ============ A: fused LayerNorm + QKV GEMM ============
// grid 256 (4 nodes/block), 384 threads (one output column each: 0-127 q,
// 128-255 k, 256-383 v). Weights staged in smem in 32-row chunks.
#define QKV_SM_FLOATS (512 + 32*384)    // hs[4][128] + ws[32][384] = 12800 fl

__global__ __launch_bounds__(384) void k_qkv2(
    const float* __restrict__ x,
    const float* __restrict__ Wq, const float* __restrict__ bq,
    const float* __restrict__ Wk, const float* __restrict__ bk,
    const float* __restrict__ Wv, const float* __restrict__ bv,
    const float* __restrict__ gamma, const float* __restrict__ beta)
{
    extern __shared__ float sm2[];
    float* hs = sm2;            // [4][128]
    float* ws = sm2 + 512;      // [32][384]
    int tid = threadIdx.x;
    int n0 = blockIdx.x * 4;
    int w = tid >> 5, lane = tid & 31;

    if (w < 4) {   // LayerNorm: warp w handles node n0+w
        float4 xa = ((const float4*)(x + (size_t)(n0 + w)*128))[lane];
        float s  = xa.x + xa.y + xa.z + xa.w;
        float s2 = xa.x*xa.x + xa.y*xa.y + xa.z*xa.z + xa.w*xa.w;
        #pragma unroll
        for (int o = 16; o; o >>= 1) {
            s  += __shfl_xor_sync(0xffffffffu, s,  o);
            s2 += __shfl_xor_sync(0xffffffffu, s2, o);
        }
        float mu  = s * (1.0f/128.0f);
        float var = s2 * (1.0f/128.0f) - mu*mu;
        float rs  = rsqrtf(var + 1e-5f);
        float4 gv = ((const float4*)gamma)[lane];
        float4 bt = ((const float4*)beta)[lane];
        float4 hv;
        hv.x = (xa.x - mu)*rs*gv.x + bt.x;
        hv.y = (xa.y - mu)*rs*gv.y + bt.y;
        hv.z = (xa.z - mu)*rs*gv.z + bt.z;
        hv.w = (xa.w - mu)*rs*gv.w + bt.w;
        ((float4*)(hs + w*128))[lane] = hv;
    }

    int col = tid, mtx = col >> 7, wcol = col & 127;
    const float* Wm = (mtx == 0) ? Wq : (mtx == 1) ? Wk : Wv;
    float bias = (mtx == 0) ? bq[wcol] : (mtx == 1) ? bk[wcol] : bv[wcol];
    float acc[4];
    #pragma unroll
    for (int i = 0; i < 4; i++) acc[i] = 0.f;

    #pragma unroll
    for (int kc = 0; kc < 4; kc++) {
        int j0 = kc * 32;
        __syncthreads();
        #pragma unroll
        for (int i = 0; i < 32; i++)
            ws[i*384 + tid] = Wm[(size_t)(j0 + i)*128 + wcol];
        __syncthreads();
        #pragma unroll
        for (int jg = 0; jg < 8; jg++) {
            int j = j0 + jg*4;
            float4 h0 = *(const float4*)(hs + 0*128 + j);
            float4 h1 = *(const float4*)(hs + 1*128 + j);
            float4 h2 = *(const float4*)(hs + 2*128 + j);
            float4 h3 = *(const float4*)(hs + 3*128 + j);
            float w0 = ws[(jg*4+0)*384 + tid];
            float w1 = ws[(jg*4+1)*384 + tid];
            float w2 = ws[(jg*4+2)*384 + tid];
            float w3 = ws[(jg*4+3)*384 + tid];
            acc[0] += h0.x*w0 + h0.y*w1 + h0.z*w2 + h0.w*w3;
            acc[1] += h1.x*w0 + h1.y*w1 + h1.z*w2 + h1.w*w3;
            acc[2] += h2.x*w0 + h2.y*w1 + h2.z*w2 + h2.w*w3;
            acc[3] += h3.x*w0 + h3.y*w1 + h3.z*w2 + h3.w*w3;
        }
    }
    float scale = (mtx == 0) ? 0.25f : 1.0f;   // q pre-scaled by 1/sqrt(dk)
    float* dst = (mtx == 0) ? g_q : (mtx == 1) ? g_k : g_v;
    #pragma unroll
    for (int nn = 0; nn < 4; nn++)
        dst[(size_t)(n0 + nn)*128 + wcol] = (acc[nn] + bias) * scale;
}

// ============ FUSED: logits + exp + S/den/av (packed f32x2) ============
// grid 256: bn = b&31 (32-n tile), bs = b>>5 (m-split of 128 m).
// 256 threads: h = tid&7, nl = tid>>3. Thread owns (n,h); w stays in regs.
// Edge rows read directly via LDG (no smem staging) -> 46 KB smem, 2 blocks/SM.
__global__ __launch_bounds__(256, 2) void k_fused(
    const float* __restrict__ edge, const int* __restrict__ mask,
    const float* __restrict__ Wae, const float* __restrict__ bae)
{
    extern __shared__ float sm[];
    float* ks = sm + K_OFF;
    float* vs = sm + V_OFF;
    int*   ms = (int*)(sm + M_OFF);

    int tid = threadIdx.x;
    int h = tid & 7, nl = tid >> 3;
    int bn = blockIdx.x & 31, bs = blockIdx.x >> 5;
    int n0 = bn * TN;
    int n  = n0 + nl;

    ull qr2[8];
    {
        const ulonglong2* qp = (const ulonglong2*)(g_q + (size_t)n*128 + h*16);
        ulonglong2 a = qp[0], b = qp[1], c = qp[2], d = qp[3];
        qr2[0]=a.x; qr2[1]=a.y; qr2[2]=b.x; qr2[3]=b.y;
        qr2[4]=c.x; qr2[5]=c.y; qr2[6]=d.x; qr2[7]=d.y;
    }
    ull wae2[8];
    #pragma unroll
    for (int e = 0; e < 8; e++) wae2[e] = pk2(Wae[(2*e)*8 + h], Wae[(2*e+1)*8 + h]);
    float baeR = bae[h];

    ull S2[8], av2[8];
    float den = 0.f;
    #pragma unroll
    for (int i = 0; i < 8; i++) { S2[i] = 0ull; av2[i] = 0ull; }

    const float* erow = edge + ((size_t)n*NN + bs*128) * 16;   // this thread's edge base

    for (int ch = 0; ch < CHUNKS; ch++) {
        int m0 = bs*128 + ch*TM;
        __syncthreads();
        // stage k,v (32m x 128), h-stride 20, m-stride 164 (conflict-free reads)
        #pragma unroll
        for (int i = 0; i < 4; i++) {
            int f = tid + i*256;
            int mm = f >> 5, c4 = f & 31;
            int hh = c4 >> 2, dd = c4 & 3;
            *(float4*)(ks + mm*164 + hh*20 + dd*4) =
                ((const float4*)(g_k + (size_t)(m0+mm)*128))[c4];
            *(float4*)(vs + mm*164 + hh*20 + dd*4) =
                ((const float4*)(g_v + (size_t)(m0+mm)*128))[c4];
        }
        // stage mask (32n x 32m)
        #pragma unroll
        for (int i = 0; i < 4; i++) {
            int f = tid + i*256;
            int nn = f >> 5, mm = f & 31;
            ms[nn*33 + mm] = mask[(size_t)(n0+nn)*NN + m0 + mm];
        }
        __syncthreads();

        const int* mrow = ms + nl*33;
        #pragma unroll 4
        for (int m = 0; m < TM; m++) {
            int mg = ch*TM + m;       // m offset within this split's 128 range
            ull ev2[8], kv2[8];
            {   // direct global load of edge row (L1-dedup across h lanes)
                const ulonglong2* ep = (const ulonglong2*)(erow + (size_t)mg*16);
                ulonglong2 a = ep[0], b = ep[1], c = ep[2], d = ep[3];
                ev2[0]=a.x; ev2[1]=a.y; ev2[2]=b.x; ev2[3]=b.y;
                ev2[4]=c.x; ev2[5]=c.y; ev2[6]=d.x; ev2[7]=d.y;
            }
            {
                const ulonglong2* kp = (const ulonglong2*)(ks + m*164 + h*20);
                ulonglong2 a = kp[0], b = kp[1], c = kp[2], d = kp[3];
                kv2[0]=a.x; kv2[1]=a.y; kv2[2]=b.x; kv2[3]=b.y;
                kv2[4]=c.x; kv2[5]=c.y; kv2[6]=d.x; kv2[7]=d.y;
            }
            // bias dot (2 chains) + qk dot (2 chains), packed
            ull t0 = 0ull, t1 = 0ull, u0 = 0ull, u1 = 0ull;
            #pragma unroll
            for (int e = 0; e < 8; e += 2) {
                t0 = fma2(ev2[e],   wae2[e],   t0);
                t1 = fma2(ev2[e+1], wae2[e+1], t1);
                u0 = fma2(qr2[e],   kv2[e],    u0);
                u1 = fma2(qr2[e+1], kv2[e+1],  u1);
            }
            ull su = add2(add2(t0, t1), add2(u0, u1));
            float lo, hi; upk2(lo, hi, su);
            float logit = lo + hi + baeR;
            float wv = mrow[m] ? __expf(logit) : 0.0f;
            den += wv;
            ull w2 = pk2(wv, wv);
            #pragma unroll
            for (int i = 0; i < 8; i++) S2[i] = fma2(w2, ev2[i], S2[i]);
            {
                const ulonglong2* vp = (const ulonglong2*)(vs + m*164 + h*20);
                ulonglong2 a = vp[0], b = vp[1], c = vp[2], d = vp[3];
                av2[0] = fma2(w2, a.x, av2[0]);
                av2[1] = fma2(w2, a.y, av2[1]);
                av2[2] = fma2(w2, b.x, av2[2]);
                av2[3] = fma2(w2, b.y, av2[3]);
                av2[4] = fma2(w2, c.x, av2[4]);
                av2[5] = fma2(w2, c.y, av2[5]);
                av2[6] = fma2(w2, d.x, av2[6]);
                av2[7] = fma2(w2, d.y, av2[7]);
            }
        }
    }

    // write partials (deterministic; combined in k_out)
    ulonglong2* Sp = (ulonglong2*)(g_Sp  + ((size_t)bs*NN + n)*128 + h*16);
    ulonglong2* Ap = (ulonglong2*)(g_avp + ((size_t)bs*NN + n)*128 + h*16);
    #pragma unroll
    for (int i = 0; i < 4; i++) {
        ulonglong2 sv; sv.x = S2[2*i];  sv.y = S2[2*i+1];  Sp[i] = sv;
        ulonglong2 av; av.x = av2[2*i]; av.y = av2[2*i+1]; Ap[i] = av;
    }
    g_dnp[((size_t)bs*NN + n)*8 + h] = den;
}

// ============ E: combine partials + edge term + Wo + residual ============
__global__ __launch_bounds__(128) void k_out(
    const float* __restrict__ x,
    const float* __restrict__ Wve, const float* __restrict__ bve,
    const float* __restrict__ Wo, const float* __restrict__ bo,
    float* __restrict__ out)
{
    __shared__ float Ss[128], attS[128], denS[8];
    int nq = blockIdx.x, c = threadIdx.x, hh = c >> 4;
    float s = 0.f, a = 0.f;
    #pragma unroll
    for (int p = 0; p < MSPLIT; p++) {
        s += g_Sp [((size_t)p*NN + nq)*128 + c];
        a += g_avp[((size_t)p*NN + nq)*128 + c];
    }
    Ss[c] = s;
    if (c < 8) {
        float dn = 0.f;
        #pragma unroll
        for (int p = 0; p < MSPLIT; p++) dn += g_dnp[((size_t)p*NN + nq)*8 + c];
        denS[c] = dn;
    }
    __syncthreads();
    float acc = a;
    #pragma unroll
    for (int e = 0; e < 16; e++) acc += Ss[hh*16 + e] * Wve[e*128 + c];
    float att = acc / denS[hh] + bve[c];
    attS[c] = att;
    __syncthreads();
    float o = bo[c];
    #pragma unroll 8
    for (int j = 0; j < 128; j++) o += attS[j] * Wo[j*128 + c];
    out[(size_t)nq*128 + c] = x[(size_t)nq*128 + c] + o;
}

// ================= launcher =================
extern "C" void kernel_launch(void* const* d_in, const int* in_sizes, int n_in,
                              void* d_out, int out_size)
{
    const float* x     = (const float*)d_in[0];
    const float* edge  = (const float*)d_in[1];
    const int*   mask  = (const int*)  d_in[2];
    const float* Wq    = (const float*)d_in[3];
    const float* bq    = (const float*)d_in[4];
    const float* Wk    = (const float*)d_in[5];
    const float* bk    = (const float*)d_in[6];
    const float* Wv    = (const float*)d_in[7];
    const float* bv    = (const float*)d_in[8];
    const float* Wae   = (const float*)d_in[9];
    const float* bae   = (const float*)d_in[10];
    const float* Wve   = (const float*)d_in[11];
    const float* bve   = (const float*)d_in[12];
    const float* Wo    = (const float*)d_in[13];
    const float* bo    = (const float*)d_in[14];
    const float* gamma = (const float*)d_in[15];
    const float* beta  = (const float*)d_in[16];
    float* out = (float*)d_out;

    cudaFuncSetAttribute(k_qkv2, cudaFuncAttributeMaxDynamicSharedMemorySize,
                         QKV_SM_FLOATS * 4);
    cudaFuncSetAttribute(k_fused, cudaFuncAttributeMaxDynamicSharedMemorySize,
                         SM_FLOATS * 4);

    k_qkv2<<<256, 384, QKV_SM_FLOATS * 4>>>(x, Wq, bq, Wk, bk, Wv, bv, gamma, beta);
    k_fused<<<256, 256, SM_FLOATS * 4>>>(edge, mask, Wae, bae);
    k_out<<<1024, 128>>>(x, Wve, bve, Wo, bo, out);
}